// round 5
// baseline (speedup 1.0000x reference)
#include <cuda_runtime.h>

#define N_NODES 100000
#define N_EDGES 3200000
#define IN_DIM  128
#define HID     16

// Scratch (device globals: allocation-free per harness rules).
// __align__(16) is required: these are accessed as float4 / red.v4.
__device__ __align__(16) float g_dinv[N_NODES];        // deg accum, then rsqrt(deg+1)
__device__ __align__(16) float g_h1  [N_NODES * HID];  // x @ W1
__device__ __align__(16) float g_agg1[N_NODES * HID];  // layer-1 aggregation
__device__ __align__(16) float g_h2  [N_NODES * HID];  // relu(agg1+b1) @ W2
__device__ int g_is64;                                  // edge_index dtype flag

// ---------------------------------------------------------------------------
// K0: detect edge_index dtype. For int64 node ids (< 2^31), every high 32-bit
// word is zero. For int32 data, words are uniform ids in [0, 1e5): the chance
// all 64 sampled odd words are zero is ~1e-320. Reads 512B (safe for both).
__global__ void k_detect(const unsigned int* __restrict__ ei32) {
    int is64 = 1;
    #pragma unroll
    for (int i = 0; i < 64; i++)
        if (ei32[2 * i + 1] != 0u) { is64 = 0; break; }
    g_is64 = is64;
}

__device__ __forceinline__ void load_edge(const void* __restrict__ ei, int e,
                                          int& s, int& d, int is64) {
    if (is64) {
        const long long* p = (const long long*)ei;
        s = (int)p[e];
        d = (int)p[N_EDGES + e];
    } else {
        const int* p = (const int*)ei;
        s = p[e];
        d = p[N_EDGES + e];
    }
}

// K1: zero degree accumulator
__global__ void k_zero_deg() {
    int i = blockIdx.x * blockDim.x + threadIdx.x;
    if (i < N_NODES) g_dinv[i] = 0.0f;
}

// K2: count in-degree over dst
__global__ void k_deg(const void* __restrict__ ei) {
    int e = blockIdx.x * blockDim.x + threadIdx.x;
    if (e < N_EDGES) {
        const int is64 = g_is64;
        int d;
        if (is64) d = (int)((const long long*)ei)[N_EDGES + e];
        else      d = ((const int*)ei)[N_EDGES + e];
        atomicAdd(&g_dinv[d], 1.0f);
    }
}

// K3: dinv = rsqrt(deg + 1)   (+1 = self loop; always > 0)
__global__ void k_dinv() {
    int i = blockIdx.x * blockDim.x + threadIdx.x;
    if (i < N_NODES) g_dinv[i] = rsqrtf(g_dinv[i] + 1.0f);
}

// K4: h1 = x @ W1 ; agg1 = h1 * dinv^2 (self-loop init)
// 256 threads/block, 16 rows/block. N_NODES % 16 == 0.
__global__ void k_gemm1(const float* __restrict__ x, const float* __restrict__ W1) {
    __shared__ float xs[16][IN_DIM];   // 8 KB
    __shared__ float ws[IN_DIM][HID];  // 8 KB
    const int t = threadIdx.x;
    const int row0 = blockIdx.x * 16;

    #pragma unroll
    for (int i = t; i < IN_DIM * HID; i += 256)
        ws[i >> 4][i & 15] = W1[i];
    #pragma unroll
    for (int i = t; i < 16 * IN_DIM; i += 256)
        xs[i >> 7][i & 127] = x[row0 * IN_DIM + i];
    __syncthreads();

    const int r = t >> 4, c = t & 15;
    float s = 0.0f;
    #pragma unroll
    for (int k = 0; k < IN_DIM; k++)
        s = fmaf(xs[r][k], ws[k][c], s);

    const int node = row0 + r;
    const float di = g_dinv[node];
    g_h1[node * HID + c]   = s;
    g_agg1[node * HID + c] = s * di * di;
}

// ---------------------------------------------------------------------------
// Vectorized edge scatter: 4 threads per edge. Each thread handles one quad
// (float4) of the 16-wide feature row: LDG.128 gather from src row, scale by
// norm, one red.global.add.v4.f32 into the dst row.
__device__ __forceinline__ void red_add_v4(float* addr, float4 v) {
    asm volatile("red.global.add.v4.f32 [%0], {%1, %2, %3, %4};"
                 :: "l"(addr), "f"(v.x), "f"(v.y), "f"(v.z), "f"(v.w)
                 : "memory");
}

// K5: edge scatter, layer 1: agg1[dst] += h1[src] * dinv[src]*dinv[dst]
__global__ void k_scatter1(const void* __restrict__ ei) {
    unsigned int gid = blockIdx.x * blockDim.x + threadIdx.x;
    if (gid >= (unsigned int)N_EDGES * 4u) return;
    const int e = gid >> 2;
    const int q = gid & 3;
    int s, d;
    load_edge(ei, e, s, d, g_is64);
    const float norm = g_dinv[s] * g_dinv[d];
    float4 v = reinterpret_cast<const float4*>(g_h1)[s * 4 + q];
    v.x *= norm; v.y *= norm; v.z *= norm; v.w *= norm;
    red_add_v4(&g_agg1[d * HID + q * 4], v);
}

// K6: h2 = relu(agg1 + b1) @ W2 ; out = h2 * dinv^2 + b2 (self-loop + bias init)
__global__ void k_gemm2(const float* __restrict__ W2,
                        const float* __restrict__ b1,
                        const float* __restrict__ b2,
                        float* __restrict__ out) {
    __shared__ float hs[16][HID];
    __shared__ float ws[HID][HID];
    const int t = threadIdx.x;
    const int r = t >> 4, c = t & 15;

    ws[r][c] = W2[t];                          // 256 == 16*16
    const int node = blockIdx.x * 16 + r;
    hs[r][c] = fmaxf(g_agg1[node * HID + c] + b1[c], 0.0f);
    __syncthreads();

    float s = 0.0f;
    #pragma unroll
    for (int k = 0; k < HID; k++)
        s = fmaf(hs[r][k], ws[k][c], s);

    const float di = g_dinv[node];
    g_h2[node * HID + c] = s;
    out[node * HID + c]  = s * di * di + b2[c];
}

// K7: edge scatter, layer 2: out[dst] += h2[src] * dinv[src]*dinv[dst]
__global__ void k_scatter2(const void* __restrict__ ei, float* __restrict__ out) {
    unsigned int gid = blockIdx.x * blockDim.x + threadIdx.x;
    if (gid >= (unsigned int)N_EDGES * 4u) return;
    const int e = gid >> 2;
    const int q = gid & 3;
    int s, d;
    load_edge(ei, e, s, d, g_is64);
    const float norm = g_dinv[s] * g_dinv[d];
    float4 v = reinterpret_cast<const float4*>(g_h2)[s * 4 + q];
    v.x *= norm; v.y *= norm; v.z *= norm; v.w *= norm;
    red_add_v4(&out[d * HID + q * 4], v);
}

extern "C" void kernel_launch(void* const* d_in, const int* in_sizes, int n_in,
                              void* d_out, int out_size) {
    const float* x   = (const float*)d_in[0];
    const void*  ei  = d_in[1];                 // [2, E] int64 OR int32 (detected)
    const float* W1  = (const float*)d_in[2];
    const float* b1  = (const float*)d_in[3];
    const float* W2  = (const float*)d_in[4];
    const float* b2  = (const float*)d_in[5];
    float*       out = (float*)d_out;

    const int nodeBlocks = (N_NODES + 255) / 256;
    const int edgeBlocks = (N_EDGES + 255) / 256;
    const int rowBlocks  = N_NODES / 16;                        // 6250
    const unsigned int scatWork = (unsigned int)N_EDGES * 4u;   // 12.8M
    const int scatBlocks = (int)((scatWork + 255u) / 256u);     // 50000

    k_detect  <<<1, 1>>>((const unsigned int*)ei);
    k_zero_deg<<<nodeBlocks, 256>>>();
    k_deg     <<<edgeBlocks, 256>>>(ei);
    k_dinv    <<<nodeBlocks, 256>>>();
    k_gemm1   <<<rowBlocks, 256>>>(x, W1);
    k_scatter1<<<scatBlocks, 256>>>(ei);
    k_gemm2   <<<rowBlocks, 256>>>(W2, b1, b2, out);
    k_scatter2<<<scatBlocks, 256>>>(ei, out);
}

// round 10
// speedup vs baseline: 1.0881x; 1.0881x over previous
#include <cuda_runtime.h>

#define N_NODES 100000
#define N_EDGES 3200000
#define IN_DIM  128
#define HID     16
#define SB1     512
#define SCAN_BLOCKS ((N_NODES + SB1 - 1) / SB1)   // 196

// Scratch (device globals, ~19.6 MB). CRITICAL RULE (root cause of rounds
// 6-9 failures): NEVER pass a __device__ symbol as a kernel argument from
// host code — the host-side shadow address gets passed, the kernel derefs a
// host VA, and HMM backs it with a 128 MiB device arena, tripping the
// harness mem-guard. All globals are referenced directly in device code.
__device__ __align__(16) float g_buf[N_NODES * HID];   // h1, then h2 (6.4 MB)
__device__ int g_srcs  [N_EDGES];                      // dst-sorted src ids (12.8 MB)
__device__ int g_cursor[N_NODES];                      // hist -> excl -> incl prefix
__device__ int g_bsum [SCAN_BLOCKS];
__device__ int g_bbase[256];
__device__ int g_is64;

// ---------------------------------------------------------------------------
// K0: detect edge_index dtype (int64 ids < 2^31 -> all odd 32-bit words zero).
__global__ void k_detect(const unsigned int* __restrict__ ei32) {
    int is64 = 1;
    #pragma unroll
    for (int i = 0; i < 64; i++)
        if (ei32[2 * i + 1] != 0u) { is64 = 0; break; }
    g_is64 = is64;
}

__global__ void k_zero() {
    int i = blockIdx.x * blockDim.x + threadIdx.x;
    if (i < N_NODES) g_cursor[i] = 0;
}

// K2: in-degree histogram over dst (into g_cursor)
__global__ void k_hist(const void* __restrict__ ei) {
    int e = blockIdx.x * blockDim.x + threadIdx.x;
    if (e < N_EDGES) {
        int d;
        if (g_is64) d = (int)((const long long*)ei)[N_EDGES + e];
        else        d = ((const int*)ei)[N_EDGES + e];
        atomicAdd(&g_cursor[d], 1);
    }
}

// K3a: per-block exclusive scan of g_cursor IN PLACE; block sums -> g_bsum
__global__ void k_scan1() {
    __shared__ int sh[SB1];
    const int t = threadIdx.x;
    const int i = blockIdx.x * SB1 + t;
    int v = (i < N_NODES) ? g_cursor[i] : 0;
    sh[t] = v;
    __syncthreads();
    #pragma unroll
    for (int o = 1; o < SB1; o <<= 1) {
        int a = (t >= o) ? sh[t - o] : 0;
        __syncthreads();
        sh[t] += a;
        __syncthreads();
    }
    if (i < N_NODES) g_cursor[i] = sh[t] - v;            // local exclusive
    if (t == SB1 - 1) g_bsum[blockIdx.x] = sh[SB1 - 1];  // block total
}

// K3b: scan the block sums (single block, 256 >= 196)
__global__ void k_scan2() {
    __shared__ int sh[256];
    const int t = threadIdx.x;
    int v = (t < SCAN_BLOCKS) ? g_bsum[t] : 0;
    sh[t] = v;
    __syncthreads();
    #pragma unroll
    for (int o = 1; o < 256; o <<= 1) {
        int a = (t >= o) ? sh[t - o] : 0;
        __syncthreads();
        sh[t] += a;
        __syncthreads();
    }
    g_bbase[t] = sh[t] - v;
}

// K3c: add block bases -> global exclusive prefix (= segment starts)
__global__ void k_scan3() {
    int i = blockIdx.x * blockDim.x + threadIdx.x;
    if (i < N_NODES) g_cursor[i] += g_bbase[i / SB1];
}

// K4: permute src ids into dst-sorted order. Cursors advance from exclusive
// prefix (start) to inclusive prefix (end); agg reconstructs cnt from diffs.
__global__ void k_permute(const void* __restrict__ ei) {
    int e = blockIdx.x * blockDim.x + threadIdx.x;
    if (e >= N_EDGES) return;
    int s, d;
    if (g_is64) {
        const long long* p = (const long long*)ei;
        s = (int)p[e]; d = (int)p[N_EDGES + e];
    } else {
        const int* p = (const int*)ei;
        s = p[e]; d = p[N_EDGES + e];
    }
    int pos = atomicAdd(&g_cursor[d], 1);
    g_srcs[pos] = s;
}

// in-degree of node i from inclusive-prefix cursor; dinv = rsqrt(deg+1)
__device__ __forceinline__ float dinv_of(int i) {
    int end   = g_cursor[i];
    int start = (i == 0) ? 0 : g_cursor[i - 1];
    return rsqrtf((float)(end - start) + 1.0f);
}

// K5: h1 = x @ W1 -> g_buf. 16 rows/block, 256 threads.
__global__ void k_gemm1(const float* __restrict__ x, const float* __restrict__ W1) {
    __shared__ float xs[16][IN_DIM];
    __shared__ float ws[IN_DIM][HID];
    const int t = threadIdx.x;
    const int row0 = blockIdx.x * 16;

    #pragma unroll
    for (int i = t; i < IN_DIM * HID; i += 256)
        ws[i >> 4][i & 15] = W1[i];
    #pragma unroll
    for (int i = t; i < 16 * IN_DIM; i += 256)
        xs[i >> 7][i & 127] = x[row0 * IN_DIM + i];
    __syncthreads();

    const int r = t >> 4, c = t & 15;
    float s = 0.0f;
    #pragma unroll
    for (int k = 0; k < IN_DIM; k++)
        s = fmaf(xs[r][k], ws[k][c], s);
    g_buf[(row0 + r) * HID + c] = s;
}

// ---------------------------------------------------------------------------
// K6: segmented aggregation, warp per node, no atomics. Reads h from g_buf
// (device symbol, referenced directly — NOT a kernel argument).
// dst[node] = (relu?)( bias + dinv^2*h[node] + sum_e h[src]*dinv[src]*dinv[node] )
// Lanes cooperatively load 32 src ids + recompute dinv from cursor diffs;
// 4 rounds of 8 edges: lane handles edge j=(lane>>2)+8r (shfl) and quad
// q=lane&3 (one LDG.128 gather). shfl_xor reduce; lanes 0-3 store the row.
__global__ void k_agg(const float* __restrict__ bias,
                      float* __restrict__ dst,
                      int relu) {
    const int warp = (blockIdx.x * blockDim.x + threadIdx.x) >> 5;
    if (warp >= N_NODES) return;
    const float* __restrict__ h = g_buf;
    const int lane = threadIdx.x & 31;
    const int node = warp;
    const int end   = g_cursor[node];
    const int start = (node == 0) ? 0 : g_cursor[node - 1];
    const int cnt   = end - start;
    const int q     = lane & 3;
    const float dnode = rsqrtf((float)cnt + 1.0f);

    float4 acc = make_float4(0.f, 0.f, 0.f, 0.f);

    for (int base = 0; base < cnt; base += 32) {
        const int m = cnt - base;             // valid edges in this chunk
        int   src_l = 0;
        float nm_l  = 0.0f;                   // 0 => inert
        if (lane < m) {
            src_l = g_srcs[start + base + lane];
            nm_l  = dinv_of(src_l) * dnode;
        }
        #pragma unroll
        for (int r = 0; r < 4; r++) {
            if (8 * r >= m) break;            // uniform per warp
            const int j = (lane >> 2) + 8 * r;
            const int   src = __shfl_sync(0xffffffffu, src_l, j);
            const float nm  = __shfl_sync(0xffffffffu, nm_l,  j);
            float4 v = reinterpret_cast<const float4*>(h)[src * 4 + q];
            acc.x = fmaf(v.x, nm, acc.x);
            acc.y = fmaf(v.y, nm, acc.y);
            acc.z = fmaf(v.z, nm, acc.z);
            acc.w = fmaf(v.w, nm, acc.w);
        }
    }

    // reduce over edge-slots (lanes with equal lane&3)
    #pragma unroll
    for (int ofs = 4; ofs < 32; ofs <<= 1) {
        acc.x += __shfl_xor_sync(0xffffffffu, acc.x, ofs);
        acc.y += __shfl_xor_sync(0xffffffffu, acc.y, ofs);
        acc.z += __shfl_xor_sync(0xffffffffu, acc.z, ofs);
        acc.w += __shfl_xor_sync(0xffffffffu, acc.w, ofs);
    }

    if (lane < 4) {
        const float d2 = dnode * dnode;
        float4 self = reinterpret_cast<const float4*>(h)[node * 4 + lane];
        float4 bv   = reinterpret_cast<const float4*>(bias)[lane];
        float4 o;
        o.x = fmaf(self.x, d2, acc.x) + bv.x;
        o.y = fmaf(self.y, d2, acc.y) + bv.y;
        o.z = fmaf(self.z, d2, acc.z) + bv.z;
        o.w = fmaf(self.w, d2, acc.w) + bv.w;
        if (relu) {
            o.x = fmaxf(o.x, 0.f); o.y = fmaxf(o.y, 0.f);
            o.z = fmaxf(o.z, 0.f); o.w = fmaxf(o.w, 0.f);
        }
        reinterpret_cast<float4*>(dst)[node * 4 + lane] = o;
    }
}

// K7: h2 = act @ W2. act lives in d_out (harness pointer, legal arg);
// result overwrites g_buf directly (h1 is dead).
__global__ void k_gemm2(const float* __restrict__ act, const float* __restrict__ W2) {
    __shared__ float hs[16][HID];
    __shared__ float ws[HID][HID];
    const int t = threadIdx.x;
    const int r = t >> 4, c = t & 15;
    ws[r][c] = W2[t];
    const int node = blockIdx.x * 16 + r;
    hs[r][c] = act[node * HID + c];
    __syncthreads();
    float s = 0.0f;
    #pragma unroll
    for (int k = 0; k < HID; k++)
        s = fmaf(hs[r][k], ws[k][c], s);
    g_buf[node * HID + c] = s;
}

extern "C" void kernel_launch(void* const* d_in, const int* in_sizes, int n_in,
                              void* d_out, int out_size) {
    const float* x   = (const float*)d_in[0];
    const void*  ei  = d_in[1];                 // [2,E] int64 OR int32 (detected)
    const float* W1  = (const float*)d_in[2];
    const float* b1  = (const float*)d_in[3];
    const float* W2  = (const float*)d_in[4];
    const float* b2  = (const float*)d_in[5];
    float*       out = (float*)d_out;

    const int nodeBlocks = (N_NODES + 255) / 256;          // 391
    const int edgeBlocks = (N_EDGES + 255) / 256;          // 12500
    const int rowBlocks  = N_NODES / 16;                   // 6250
    const int aggBlocks  = (N_NODES * 32 + 255) / 256;     // 12500

    k_detect <<<1, 1>>>((const unsigned int*)ei);
    k_zero   <<<nodeBlocks, 256>>>();
    k_hist   <<<edgeBlocks, 256>>>(ei);
    k_scan1  <<<SCAN_BLOCKS, SB1>>>();
    k_scan2  <<<1, 256>>>();
    k_scan3  <<<nodeBlocks, 256>>>();
    k_permute<<<edgeBlocks, 256>>>(ei);
    k_gemm1  <<<rowBlocks, 256>>>(x, W1);
    k_agg    <<<aggBlocks, 256>>>(b1, out, 1);   // act -> d_out (scratch)
    k_gemm2  <<<rowBlocks, 256>>>(out, W2);      // h2 -> g_buf
    k_agg    <<<aggBlocks, 256>>>(b2, out, 0);   // final -> d_out
}

// round 11
// speedup vs baseline: 1.2387x; 1.1384x over previous
#include <cuda_runtime.h>

#define N_NODES 100000
#define N_EDGES 3200000
#define IN_DIM  128
#define HID     16
#define SB1     512
#define SCAN_BLOCKS ((N_NODES + SB1 - 1) / SB1)   // 196

// Scratch (device globals, ~19.6 MB). CRITICAL RULE (root cause of rounds
// 6-9 failures): NEVER pass a __device__ symbol as a kernel argument from
// host code — the host-side shadow address gets passed, the kernel derefs a
// host VA, and HMM backs it with a 128 MiB device arena, tripping the
// harness mem-guard. All globals are referenced directly in device code.
__device__ __align__(16) float g_buf[N_NODES * HID];   // hs1, then hs2 (6.4 MB)
__device__ int g_srcs  [N_EDGES];                      // dst-sorted src ids (12.8 MB)
__device__ int g_cursor[N_NODES];                      // hist -> excl -> incl prefix
__device__ int g_bsum [SCAN_BLOCKS];
__device__ int g_bbase[256];
__device__ int g_is64;

// ---------------------------------------------------------------------------
// K0: zero cursor; block 0 thread 0 also detects edge_index dtype
// (int64 ids < 2^31 -> all odd 32-bit words zero).
__global__ void k_zero(const unsigned int* __restrict__ ei32) {
    int i = blockIdx.x * blockDim.x + threadIdx.x;
    if (i < N_NODES) g_cursor[i] = 0;
    if (i == 0) {
        int is64 = 1;
        #pragma unroll
        for (int k = 0; k < 64; k++)
            if (ei32[2 * k + 1] != 0u) { is64 = 0; break; }
        g_is64 = is64;
    }
}

// K1: in-degree histogram over dst (into g_cursor)
__global__ void k_hist(const void* __restrict__ ei) {
    int e = blockIdx.x * blockDim.x + threadIdx.x;
    if (e < N_EDGES) {
        int d;
        if (g_is64) d = (int)((const long long*)ei)[N_EDGES + e];
        else        d = ((const int*)ei)[N_EDGES + e];
        atomicAdd(&g_cursor[d], 1);
    }
}

// K2a: per-block exclusive scan of g_cursor IN PLACE; block sums -> g_bsum
__global__ void k_scan1() {
    __shared__ int sh[SB1];
    const int t = threadIdx.x;
    const int i = blockIdx.x * SB1 + t;
    int v = (i < N_NODES) ? g_cursor[i] : 0;
    sh[t] = v;
    __syncthreads();
    #pragma unroll
    for (int o = 1; o < SB1; o <<= 1) {
        int a = (t >= o) ? sh[t - o] : 0;
        __syncthreads();
        sh[t] += a;
        __syncthreads();
    }
    if (i < N_NODES) g_cursor[i] = sh[t] - v;            // local exclusive
    if (t == SB1 - 1) g_bsum[blockIdx.x] = sh[SB1 - 1];  // block total
}

// K2b: scan the block sums (single block, 256 >= 196)
__global__ void k_scan2() {
    __shared__ int sh[256];
    const int t = threadIdx.x;
    int v = (t < SCAN_BLOCKS) ? g_bsum[t] : 0;
    sh[t] = v;
    __syncthreads();
    #pragma unroll
    for (int o = 1; o < 256; o <<= 1) {
        int a = (t >= o) ? sh[t - o] : 0;
        __syncthreads();
        sh[t] += a;
        __syncthreads();
    }
    g_bbase[t] = sh[t] - v;
}

// K2c: add block bases -> global exclusive prefix (= segment starts)
__global__ void k_scan3() {
    int i = blockIdx.x * blockDim.x + threadIdx.x;
    if (i < N_NODES) g_cursor[i] += g_bbase[i / SB1];
}

// K3: permute src ids into dst-sorted order. Cursors advance from exclusive
// prefix (start) to inclusive prefix (end); cnt reconstructed from diffs.
__global__ void k_permute(const void* __restrict__ ei) {
    int e = blockIdx.x * blockDim.x + threadIdx.x;
    if (e >= N_EDGES) return;
    int s, d;
    if (g_is64) {
        const long long* p = (const long long*)ei;
        s = (int)p[e]; d = (int)p[N_EDGES + e];
    } else {
        const int* p = (const int*)ei;
        s = p[e]; d = p[N_EDGES + e];
    }
    int pos = atomicAdd(&g_cursor[d], 1);
    g_srcs[pos] = s;
}

// dinv = rsqrt(deg+1) from inclusive-prefix cursor (+1 = self loop)
__device__ __forceinline__ float dinv_of(int i) {
    int end   = g_cursor[i];
    int start = (i == 0) ? 0 : g_cursor[i - 1];
    return rsqrtf((float)(end - start) + 1.0f);
}

// K4: hs1 = (x @ W1) * dinv[node] -> g_buf. 16 rows/block, 256 threads.
// Pre-scaling by dinv[src] here removes ALL per-edge norm work from k_agg.
__global__ void k_gemm1(const float* __restrict__ x, const float* __restrict__ W1) {
    __shared__ float xs[16][IN_DIM];
    __shared__ float ws[IN_DIM][HID];
    const int t = threadIdx.x;
    const int row0 = blockIdx.x * 16;

    #pragma unroll
    for (int i = t; i < IN_DIM * HID; i += 256)
        ws[i >> 4][i & 15] = W1[i];
    #pragma unroll
    for (int i = t; i < 16 * IN_DIM; i += 256)
        xs[i >> 7][i & 127] = x[row0 * IN_DIM + i];
    __syncthreads();

    const int r = t >> 4, c = t & 15;
    float s = 0.0f;
    #pragma unroll
    for (int k = 0; k < IN_DIM; k++)
        s = fmaf(xs[r][k], ws[k][c], s);

    const int node = row0 + r;
    g_buf[node * HID + c] = s * dinv_of(node);
}

// ---------------------------------------------------------------------------
// K5: segmented aggregation, warp per node, no atomics, no per-edge norms.
// dst[node] = (relu?)( bias + dinv[node] * ( hs[node] + sum_e hs[src_e] ) )
// Lanes cooperatively load 32 src ids; 4 rounds of 8 edges: lane handles
// edge j=(lane>>2)+8r (one shfl) and quad q=lane&3 (one LDG.128 gather).
__global__ void k_agg(const float* __restrict__ bias,
                      float* __restrict__ dst,
                      int relu) {
    const int warp = (blockIdx.x * blockDim.x + threadIdx.x) >> 5;
    if (warp >= N_NODES) return;
    const float* __restrict__ h = g_buf;    // device symbol, device-side only
    const int lane = threadIdx.x & 31;
    const int node = warp;
    const int end   = g_cursor[node];
    const int start = (node == 0) ? 0 : g_cursor[node - 1];
    const int cnt   = end - start;
    const int q     = lane & 3;
    const float dnode = rsqrtf((float)cnt + 1.0f);

    float4 acc = make_float4(0.f, 0.f, 0.f, 0.f);

    for (int base = 0; base < cnt; base += 32) {
        const int m = cnt - base;             // valid edges in this chunk
        int src_l = node;                     // inert fill: gathers own row,
        float w_l = 0.0f;                     // weight 0 -> no contribution
        if (lane < m) { src_l = g_srcs[start + base + lane]; w_l = 1.0f; }
        #pragma unroll
        for (int r = 0; r < 4; r++) {
            if (8 * r >= m) break;            // uniform per warp
            const int j = (lane >> 2) + 8 * r;
            const int   src = __shfl_sync(0xffffffffu, src_l, j);
            const float w   = __shfl_sync(0xffffffffu, w_l,   j);
            float4 v = reinterpret_cast<const float4*>(h)[src * 4 + q];
            acc.x = fmaf(v.x, w, acc.x);
            acc.y = fmaf(v.y, w, acc.y);
            acc.z = fmaf(v.z, w, acc.z);
            acc.w = fmaf(v.w, w, acc.w);
        }
    }

    // reduce over edge-slots (lanes with equal lane&3)
    #pragma unroll
    for (int ofs = 4; ofs < 32; ofs <<= 1) {
        acc.x += __shfl_xor_sync(0xffffffffu, acc.x, ofs);
        acc.y += __shfl_xor_sync(0xffffffffu, acc.y, ofs);
        acc.z += __shfl_xor_sync(0xffffffffu, acc.z, ofs);
        acc.w += __shfl_xor_sync(0xffffffffu, acc.w, ofs);
    }

    if (lane < 4) {
        float4 self = reinterpret_cast<const float4*>(h)[node * 4 + lane];
        float4 bv   = reinterpret_cast<const float4*>(bias)[lane];
        float4 o;
        o.x = fmaf(acc.x + self.x, dnode, bv.x);
        o.y = fmaf(acc.y + self.y, dnode, bv.y);
        o.z = fmaf(acc.z + self.z, dnode, bv.z);
        o.w = fmaf(acc.w + self.w, dnode, bv.w);
        if (relu) {
            o.x = fmaxf(o.x, 0.f); o.y = fmaxf(o.y, 0.f);
            o.z = fmaxf(o.z, 0.f); o.w = fmaxf(o.w, 0.f);
        }
        reinterpret_cast<float4*>(dst)[node * 4 + lane] = o;
    }
}

// K6: hs2 = (act @ W2) * dinv[node]. act lives in d_out (harness pointer);
// result overwrites g_buf directly (hs1 is dead).
__global__ void k_gemm2(const float* __restrict__ act, const float* __restrict__ W2) {
    __shared__ float hs[16][HID];
    __shared__ float ws[HID][HID];
    const int t = threadIdx.x;
    const int r = t >> 4, c = t & 15;
    ws[r][c] = W2[t];
    const int node = blockIdx.x * 16 + r;
    hs[r][c] = act[node * HID + c];
    __syncthreads();
    float s = 0.0f;
    #pragma unroll
    for (int k = 0; k < HID; k++)
        s = fmaf(hs[r][k], ws[k][c], s);
    g_buf[node * HID + c] = s * dinv_of(node);
}

extern "C" void kernel_launch(void* const* d_in, const int* in_sizes, int n_in,
                              void* d_out, int out_size) {
    const float* x   = (const float*)d_in[0];
    const void*  ei  = d_in[1];                 // [2,E] int64 OR int32 (detected)
    const float* W1  = (const float*)d_in[2];
    const float* b1  = (const float*)d_in[3];
    const float* W2  = (const float*)d_in[4];
    const float* b2  = (const float*)d_in[5];
    float*       out = (float*)d_out;

    const int nodeBlocks = (N_NODES + 255) / 256;          // 391
    const int edgeBlocks = (N_EDGES + 255) / 256;          // 12500
    const int rowBlocks  = N_NODES / 16;                   // 6250
    const int aggBlocks  = (N_NODES * 32 + 255) / 256;     // 12500

    k_zero   <<<nodeBlocks, 256>>>((const unsigned int*)ei);
    k_hist   <<<edgeBlocks, 256>>>(ei);
    k_scan1  <<<SCAN_BLOCKS, SB1>>>();
    k_scan2  <<<1, 256>>>();
    k_scan3  <<<nodeBlocks, 256>>>();
    k_permute<<<edgeBlocks, 256>>>(ei);
    k_gemm1  <<<rowBlocks, 256>>>(x, W1);
    k_agg    <<<aggBlocks, 256>>>(b1, out, 1);   // act -> d_out (scratch)
    k_gemm2  <<<rowBlocks, 256>>>(out, W2);      // hs2 -> g_buf
    k_agg    <<<aggBlocks, 256>>>(b2, out, 0);   // final -> d_out
}